// round 3
// baseline (speedup 1.0000x reference)
#include <cuda_runtime.h>
#include <cuda_fp16.h>
#include <cstdint>

// ---------------------------------------------------------------------------
// Problem constants
// ---------------------------------------------------------------------------
#define NROWS 2048      // x rows (M)
#define DIM   1024      // K
#define SCOLS 16384     // selected neurons (N)

// GEMM tiling
#define TM 128
#define TN 128
#define KCH 64                      // K per smem stage (64 fp16 = 128B/row)
#define KITERS (DIM / KCH)          // 16

// smem: 2 stages x (A 128x64 f16 + B 128x64 f16) = 2 x 32KB
#define TILE_BYTES  (128 * 128)     // 16384 per operand tile
#define STAGE_BYTES (2 * TILE_BYTES)
#define SMEM_TOTAL  (2 * STAGE_BYTES)   // 65536

// ---------------------------------------------------------------------------
// Scratch (allocation-free: __device__ globals)
// ---------------------------------------------------------------------------
__device__ __align__(256) __half g_xh[(size_t)NROWS * DIM];   // 4 MiB
__device__ __align__(256) __half g_wh[(size_t)SCOLS * DIM];   // 32 MiB
__device__ __align__(256) float  g_bias[SCOLS];

// ---------------------------------------------------------------------------
// Helpers
// ---------------------------------------------------------------------------
__device__ __forceinline__ uint32_t smem_u32(const void* p) {
    uint32_t a;
    asm("{ .reg .u64 t; cvta.to.shared.u64 t, %1; cvt.u32.u64 %0, t; }"
        : "=r"(a) : "l"(p));
    return a;
}

__device__ __forceinline__ void cp16(uint32_t dst, const void* src) {
    asm volatile("cp.async.cg.shared.global [%0], [%1], 16;"
                 :: "r"(dst), "l"(src));
}

__device__ __forceinline__ void ldmatrix_x4(uint32_t* r, uint32_t addr) {
    asm volatile("ldmatrix.sync.aligned.m8n8.x4.shared.b16 {%0,%1,%2,%3}, [%4];"
                 : "=r"(r[0]), "=r"(r[1]), "=r"(r[2]), "=r"(r[3])
                 : "r"(addr));
}

__device__ __forceinline__ void mma16816(float* c, const uint32_t* a,
                                         uint32_t b0, uint32_t b1) {
    asm volatile(
        "mma.sync.aligned.m16n8k16.row.col.f32.f16.f16.f32 "
        "{%0,%1,%2,%3}, {%4,%5,%6,%7}, {%8,%9}, {%0,%1,%2,%3};"
        : "+f"(c[0]), "+f"(c[1]), "+f"(c[2]), "+f"(c[3])
        : "r"(a[0]), "r"(a[1]), "r"(a[2]), "r"(a[3]), "r"(b0), "r"(b1));
}

// xor swizzle within a 128B-row tile: 16B-chunk ^= (row & 7)
__device__ __forceinline__ uint32_t swz(uint32_t row, uint32_t chunk) {
    return row * 128u + ((chunk ^ (row & 7u)) << 4);
}

// sample_ids dtype detection (int64 vs int32).
// ids < 65536, so if stored as int64 every odd 32-bit word is 0.
// If stored as int32, odd words are ids; all-eight-zero has prob ~(2^-16)^8.
// Reads only the first 64 bytes — safe under both layouts.
__device__ __forceinline__ long long load_id(const void* ids_raw, int s) {
    const int* i32 = (const int*)ids_raw;
    bool is64 = ((i32[1] | i32[3] | i32[5] | i32[7] |
                  i32[9] | i32[11] | i32[13] | i32[15]) == 0);
    long long id = is64 ? ((const long long*)ids_raw)[s] : (long long)i32[s];
    return id & 0xFFFFLL;   // OUT = 65536: hard OOB guard, no-op for valid ids
}

// ---------------------------------------------------------------------------
// Kernel 1: x (f32) -> g_xh (f16)
// ---------------------------------------------------------------------------
__global__ void cvt_x_kernel(const float* __restrict__ x) {
    int idx = blockIdx.x * blockDim.x + threadIdx.x;   // 2048*256 float4s
    float4 v = reinterpret_cast<const float4*>(x)[idx];
    __half2* dst = reinterpret_cast<__half2*>(g_xh);
    dst[2 * idx + 0] = __floats2half2_rn(v.x, v.y);
    dst[2 * idx + 1] = __floats2half2_rn(v.z, v.w);
}

// ---------------------------------------------------------------------------
// Kernel 2: gather W[sample_ids] -> g_wh (f16), bias[sample_ids] -> g_bias
// ---------------------------------------------------------------------------
__global__ void gather_w_kernel(const float* __restrict__ w,
                                const float* __restrict__ bias,
                                const void* __restrict__ ids_raw) {
    int s = blockIdx.x;                 // 16384 blocks
    long long id = load_id(ids_raw, s);
    const float4* src = reinterpret_cast<const float4*>(w + (size_t)id * DIM);
    __half2* dst = reinterpret_cast<__half2*>(g_wh + (size_t)s * DIM);
    int t = threadIdx.x;                // 256 threads, 1 float4 each
    float4 v = src[t];
    dst[2 * t + 0] = __floats2half2_rn(v.x, v.y);
    dst[2 * t + 1] = __floats2half2_rn(v.z, v.w);
    if (t == 0) g_bias[s] = bias[id];
}

// ---------------------------------------------------------------------------
// Kernel 3: GEMM  out[m][n] = sum_k xh[m][k]*wh[n][k] + bias_sel[n]
// 128x128 CTA tile, mma.sync m16n8k16 f16->f32, cp.async double buffer.
// 8 warps: 2 (M) x 4 (N); warp tile 64x32 = 4x4 m16n8k16 accumulators.
// ---------------------------------------------------------------------------
__global__ void __launch_bounds__(256)
gemm_kernel(float* __restrict__ out) {
    extern __shared__ char smem[];
    const uint32_t sb = smem_u32(smem);
    const int tid = threadIdx.x;
    const int wid = tid >> 5;
    const int lid = tid & 31;
    const int wm = wid >> 2;            // 0..1
    const int wn = wid & 3;             // 0..3
    const int m0 = blockIdx.x * TM;     // 16 M-blocks (x-fastest: B L2 reuse)
    const int n0 = blockIdx.y * TN;     // 128 N-blocks

    const __half* Ag = g_xh + (size_t)m0 * DIM;
    const __half* Bg = g_wh + (size_t)n0 * DIM;

    float c[4][4][4];
#pragma unroll
    for (int i = 0; i < 4; ++i)
#pragma unroll
        for (int j = 0; j < 4; ++j)
#pragma unroll
            for (int q = 0; q < 4; ++q) c[i][j][q] = 0.f;

    const int lrow = lid & 15;          // matrix row within 16
    const int lsel = lid >> 4;          // k-half select

    // ---- prefetch stage 0 ----
    {
#pragma unroll
        for (int i = 0; i < 8; ++i) {
            const int v = tid + i * 256;
            const int isB = v >> 10;
            const int vv = v & 1023;
            const int row = vv >> 3;
            const int ch = vv & 7;
            const uint32_t dst = sb + (isB ? TILE_BYTES : 0) + swz(row, ch);
            cp16(dst, (isB ? Bg : Ag) + (size_t)row * DIM + ch * 8);
        }
        asm volatile("cp.async.commit_group;");
    }

#pragma unroll 1
    for (int kb = 0; kb < KITERS; ++kb) {
        const int st = kb & 1;
        if (kb + 1 < KITERS) {
            const __half* Agk = Ag + (kb + 1) * KCH;
            const __half* Bgk = Bg + (kb + 1) * KCH;
            const uint32_t sbase = sb + ((kb + 1) & 1) * STAGE_BYTES;
#pragma unroll
            for (int i = 0; i < 8; ++i) {
                const int v = tid + i * 256;
                const int isB = v >> 10;
                const int vv = v & 1023;
                const int row = vv >> 3;
                const int ch = vv & 7;
                const uint32_t dst = sbase + (isB ? TILE_BYTES : 0) + swz(row, ch);
                cp16(dst, (isB ? Bgk : Agk) + (size_t)row * DIM + ch * 8);
            }
            asm volatile("cp.async.commit_group;");
            asm volatile("cp.async.wait_group 1;");
        } else {
            asm volatile("cp.async.wait_group 0;");
        }
        __syncthreads();

        const uint32_t abase = sb + st * STAGE_BYTES;
        const uint32_t bbase = abase + TILE_BYTES;

#pragma unroll
        for (int ks = 0; ks < 4; ++ks) {
            const int ch = ks * 2 + lsel;
            uint32_t a[4][4];
#pragma unroll
            for (int mt = 0; mt < 4; ++mt) {
                const int r = wm * 64 + mt * 16 + lrow;
                ldmatrix_x4(a[mt], abase + swz(r, ch));
            }
            uint32_t b[2][4];
#pragma unroll
            for (int nh = 0; nh < 2; ++nh) {
                const int r = wn * 32 + nh * 16 + lrow;
                ldmatrix_x4(b[nh], bbase + swz(r, ch));
            }
#pragma unroll
            for (int mt = 0; mt < 4; ++mt)
#pragma unroll
                for (int nt = 0; nt < 4; ++nt) {
                    const int nh = nt >> 1, h = nt & 1;
                    mma16816(c[mt][nt], a[mt], b[nh][h], b[nh][2 + h]);
                }
        }
        __syncthreads();   // protect buffer before next iteration's cp.async
    }

    // ---- epilogue: += bias, write f32 ----
    const int g = lid >> 2, t = lid & 3;
    const int ncol = n0 + wn * 32 + t * 2;
    float2 bias2[4];
#pragma unroll
    for (int nt = 0; nt < 4; ++nt) {
        bias2[nt].x = g_bias[ncol + nt * 8];
        bias2[nt].y = g_bias[ncol + nt * 8 + 1];
    }
#pragma unroll
    for (int mt = 0; mt < 4; ++mt) {
        const int r0 = m0 + wm * 64 + mt * 16 + g;
        float* p0 = out + (size_t)r0 * SCOLS + ncol;
        float* p1 = p0 + (size_t)8 * SCOLS;
#pragma unroll
        for (int nt = 0; nt < 4; ++nt) {
            float2 v0 = {c[mt][nt][0] + bias2[nt].x, c[mt][nt][1] + bias2[nt].y};
            float2 v1 = {c[mt][nt][2] + bias2[nt].x, c[mt][nt][3] + bias2[nt].y};
            *reinterpret_cast<float2*>(p0 + nt * 8) = v0;
            *reinterpret_cast<float2*>(p1 + nt * 8) = v1;
        }
    }
}

// ---------------------------------------------------------------------------
// kernel_launch
// inputs (metadata order): x f32[2048*1024], weight f32[65536*1024],
//                          bias f32[65536], sample_ids int (32 or 64)[16384]
// output: f32[2048*16384]
// ---------------------------------------------------------------------------
extern "C" void kernel_launch(void* const* d_in, const int* in_sizes, int n_in,
                              void* d_out, int out_size) {
    const float* x = (const float*)d_in[0];
    const float* w = (const float*)d_in[1];
    const float* bias = (const float*)d_in[2];
    const void* ids = d_in[3];
    float* out = (float*)d_out;

    cudaFuncSetAttribute(gemm_kernel,
                         cudaFuncAttributeMaxDynamicSharedMemorySize, SMEM_TOTAL);

    cvt_x_kernel<<<NROWS, 256>>>(x);
    gather_w_kernel<<<SCOLS, 256>>>(w, bias, ids);
    dim3 grid(NROWS / TM, SCOLS / TN);      // (16, 128)
    gemm_kernel<<<grid, 256, SMEM_TOTAL>>>(out);
}